// round 14
// baseline (speedup 1.0000x reference)
#include <cuda_runtime.h>
#include <cuda_fp16.h>
#include <cstdint>

#define CDIM 128
#define RNUM 7
#define TNUM 4
#define MAXN 100000
#define MAXE 2000000
#define NPH  (RNUM + TNUM)
#define NCHK 22
#define SROW 144
#define ATB  (128 * SROW)
#define SM_B (2 * ATB)
#define BSTAGE 32768
#define SM_ACT (SM_B + 2 * BSTAGE)
#define SM_TOT (SM_ACT + 64)

// ---------------- device scratch (zero at graph entry — invariant maintained
// by re-zeroing counters after their last read inside each graph execution) --
__device__ int  g_cnt[MAXN * RNUM];
__device__ int  g_off[MAXN * RNUM];
__device__ int  g_cur[MAXN * RNUM];
__device__ int2 g_offcnt[MAXN * RNUM];
__device__ int  g_bsum[1024];
__device__ int  g_esrc[MAXE];
__device__ int  g_tcnt[4], g_tcur[4];
__device__ int  g_perm[MAXN];
__device__ __align__(16) uint4 g_Bf[NCHK * 8 * 4 * 32];

// ---------------- helpers ----------------
__device__ __forceinline__ uint32_t smem_u32(const void* p) {
    uint32_t a;
    asm("{ .reg .u64 t; cvta.to.shared.u64 t, %1; cvt.u32.u64 %0, t; }" : "=r"(a) : "l"(p));
    return a;
}
__device__ __forceinline__ void ldmat_x4(uint32_t addr, uint32_t* r) {
    asm volatile("ldmatrix.sync.aligned.m8n8.x4.shared.b16 {%0,%1,%2,%3}, [%4];"
                 : "=r"(r[0]), "=r"(r[1]), "=r"(r[2]), "=r"(r[3]) : "r"(addr));
}
__device__ __forceinline__ void mma4(float* d, const uint32_t* a, uint32_t b0, uint32_t b1) {
    asm volatile("mma.sync.aligned.m16n8k16.row.col.f32.f16.f16.f32 "
                 "{%0,%1,%2,%3}, {%4,%5,%6,%7}, {%8,%9}, {%0,%1,%2,%3};"
                 : "+f"(d[0]), "+f"(d[1]), "+f"(d[2]), "+f"(d[3])
                 : "r"(a[0]), "r"(a[1]), "r"(a[2]), "r"(a[3]), "r"(b0), "r"(b1));
}
__device__ __forceinline__ uint32_t packh(float a, float b) {
    __half2 h = __floats2half2_rn(a, b);
    return *reinterpret_cast<uint32_t*>(&h);
}
__device__ __forceinline__ uint4 lds128(uint32_t addr) {
    uint4 v;
    asm volatile("ld.shared.v4.b32 {%0,%1,%2,%3}, [%4];"
                 : "=r"(v.x), "=r"(v.y), "=r"(v.z), "=r"(v.w) : "r"(addr));
    return v;
}
__device__ __forceinline__ void cp16(uint32_t s, const void* g) {
    asm volatile("cp.async.cg.shared.global [%0], [%1], 16;" :: "r"(s), "l"(g));
}
#define CP_COMMIT() asm volatile("cp.async.commit_group;" ::: "memory")
#define CP_WAIT1()  asm volatile("cp.async.wait_group 1;" ::: "memory")

__device__ __forceinline__ int sel4(int s, int a0, int a1, int a2, int a3) {
    int lo = (s & 1) ? a1 : a0;
    int hi = (s & 1) ? a3 : a2;
    return (s & 2) ? hi : lo;
}
__device__ __forceinline__ void storeA(uint32_t sbase, int m, int lane, float4 v) {
    int chunk = lane >> 4;
    uint32_t boff = (uint32_t)m * SROW + (lane & 15) * 8;
    uint32_t hp0 = packh(v.x, v.y), hp1 = packh(v.z, v.w);
    asm volatile("st.shared.v2.b32 [%0], {%1,%2};"
                 :: "r"(sbase + chunk * ATB + boff), "r"(hp0), "r"(hp1) : "memory");
}

// ---------------- prologue (5 launches) ----------------
__global__ void k_count_t(const int* __restrict__ ei, const int* __restrict__ et,
                          const int* __restrict__ tnt, int E, int Nn) {
    __shared__ int h[4];
    if (threadIdx.x < 4) h[threadIdx.x] = 0;
    __syncthreads();
    int i = blockIdx.x * blockDim.x + threadIdx.x;
    if (i < E) atomicAdd(&g_cnt[ei[E + i] * RNUM + et[i]], 1);
    if (i < Nn) atomicAdd(&h[tnt[i]], 1);
    __syncthreads();
    if (threadIdx.x < 4 && h[threadIdx.x]) atomicAdd(&g_tcnt[threadIdx.x], h[threadIdx.x]);
}
__global__ void k_scan1b(int nseg, int nb,
                         const float* __restrict__ rel_w,
                         const float* __restrict__ root_w) {
    if ((int)blockIdx.x >= nb) {
        int idx = ((int)blockIdx.x - nb) * 256 + threadIdx.x;
        if (idx >= NCHK * 8 * 4 * 32) return;
        int lane = idx & 31;
        int s = (idx >> 5) & 3;
        int j = (idx >> 7) & 7;
        int chunk = idx >> 10;
        uint32_t hq[4];
#pragma unroll
        for (int q = 0; q < 4; q++) {
            int n = j * 16 + ((q & 2) ? 8 : 0) + (lane >> 2);
            int kk = s * 16 + ((q & 1) ? 8 : 0) + 2 * (lane & 3);
            float w0, w1;
            if (chunk < 14) {
                int r = chunk >> 1, kb = (chunk & 1) * 64;
                const float* p = rel_w + ((size_t)(r * CDIM + n)) * CDIM + kb + kk;
                w0 = p[0]; w1 = p[1];
            } else {
                int rc = chunk - 14;
                int t = rc >> 1, kb = (rc & 1) * 64;
                const float* p = root_w + ((size_t)(t * CDIM + n)) * CDIM + kb + kk;
                w0 = p[0]; w1 = p[1];
            }
            hq[q] = packh(w0, w1);
        }
        g_Bf[(((size_t)chunk * 8 + j) * 4 + s) * 32 + lane] =
            make_uint4(hq[0], hq[1], hq[2], hq[3]);
        return;
    }
    __shared__ int wsum[8];
    int tid = threadIdx.x;
    int base = blockIdx.x * 1024 + tid * 4;
    int v0 = 0, v1 = 0, v2 = 0, v3 = 0;
    if (base + 0 < nseg) v0 = g_cnt[base + 0];
    if (base + 1 < nseg) v1 = g_cnt[base + 1];
    if (base + 2 < nseg) v2 = g_cnt[base + 2];
    if (base + 3 < nseg) v3 = g_cnt[base + 3];
    int tot = v0 + v1 + v2 + v3;
    int lane = tid & 31, wid = tid >> 5;
    int inc = tot;
#pragma unroll
    for (int d = 1; d < 32; d <<= 1) {
        int t = __shfl_up_sync(0xffffffff, inc, d);
        if (lane >= d) inc += t;
    }
    if (lane == 31) wsum[wid] = inc;
    __syncthreads();
    if (wid == 0) {
        int w = (lane < 8) ? wsum[lane] : 0;
#pragma unroll
        for (int d = 1; d < 8; d <<= 1) {
            int t = __shfl_up_sync(0xffffffff, w, d);
            if (lane >= d) w += t;
        }
        if (lane < 8) wsum[lane] = w;
    }
    __syncthreads();
    int excl = inc - tot + (wid ? wsum[wid - 1] : 0);
    if (base + 0 < nseg) g_off[base + 0] = excl;
    if (base + 1 < nseg) g_off[base + 1] = excl + v0;
    if (base + 2 < nseg) g_off[base + 2] = excl + v0 + v1;
    if (base + 3 < nseg) g_off[base + 3] = excl + v0 + v1 + v2;
    if (tid == 255) g_bsum[blockIdx.x] = wsum[7];
}
__global__ void k_scan2t(int nb) {
    __shared__ int sm[1024];
    int tid = threadIdx.x;
    int v = (tid < nb) ? g_bsum[tid] : 0;
    sm[tid] = v;
    __syncthreads();
    for (int d = 1; d < 1024; d <<= 1) {
        int t = (tid >= d) ? sm[tid - d] : 0;
        __syncthreads();
        sm[tid] += t;
        __syncthreads();
    }
    if (tid < nb) g_bsum[tid] = sm[tid] - v;
    if (tid == 0) {
        int a = g_tcnt[0], b = g_tcnt[1], c = g_tcnt[2];
        g_tcur[0] = 0; g_tcur[1] = a; g_tcur[2] = a + b; g_tcur[3] = a + b + c;
        g_tcnt[0] = 0; g_tcnt[1] = 0; g_tcnt[2] = 0; g_tcnt[3] = 0;
    }
}
__global__ void k_scan3z(int nseg) {
    int i = blockIdx.x * blockDim.x + threadIdx.x;
    if (i < nseg) {
        int v = g_off[i] + g_bsum[i >> 10];
        g_cur[i] = v;
        g_offcnt[i] = make_int2(v, g_cnt[i]);
        g_cnt[i] = 0;
    }
}
__global__ void k_scatter2(const int* __restrict__ ei, const int* __restrict__ et,
                           const int* __restrict__ tnt, int E, int Nn, int eb) {
    if ((int)blockIdx.x < eb) {
        int e = blockIdx.x * 256 + threadIdx.x;
        if (e < E) {
            int s = ei[E + e] * RNUM + et[e];
            int p = atomicAdd(&g_cur[s], 1);
            g_esrc[p] = ei[e];
        }
        return;
    }
    __shared__ int loc[4], base[4];
    if (threadIdx.x < 4) loc[threadIdx.x] = 0;
    __syncthreads();
    int i = ((int)blockIdx.x - eb) * 256 + threadIdx.x;
    int t = 0, my = 0;
    bool ok = (i < Nn);
    if (ok) { t = tnt[i]; my = atomicAdd(&loc[t], 1); }
    __syncthreads();
    if (threadIdx.x < 4) base[threadIdx.x] = atomicAdd(&g_tcur[threadIdx.x], loc[threadIdx.x]);
    __syncthreads();
    if (ok) g_perm[base[t] + my] = i;
}

// ---------------- fused: 256 threads, 2 CTAs/SM, 8-edge register pipeline ---
__global__ __launch_bounds__(256, 2) void k_fused(const float* __restrict__ x,
                                                  const int* __restrict__ tnt,
                                                  const float* __restrict__ root_b,
                                                  float* __restrict__ out, int Nn) {
    extern __shared__ char smem[];
    const uint32_t sb = smem_u32(smem);
    int* s_act = reinterpret_cast<int*>(smem + SM_ACT);
    const int tid = threadIdx.x, wid = tid >> 5, lane = tid & 31;
    const int row0 = blockIdx.x * 128;
    const int wm0 = (wid & 3) * 32;
    const int jbase = (wid >> 2) * 4;
    const int wn0 = jbase * 16;
    const int quad = lane >> 3, lrow = lane & 7;
    const int a_roff = ((quad & 1) * 8 + lrow) * SROW + ((quad >> 1) * 8) * 2;
    const float4* x4 = reinterpret_cast<const float4*>(x);

    float acc[16][4];
#pragma unroll
    for (int j = 0; j < 16; j++)
#pragma unroll
        for (int q = 0; q < 4; q++) acc[j][q] = 0.f;

    if (tid == 0) s_act[0] = 0;
    __syncthreads();

    int off_s0 = 0, cnt_s0 = 0, off_s1 = 0, cnt_s1 = 0;
    int off_s2 = 0, cnt_s2 = 0, off_s3 = 0, cnt_s3 = 0;
    int mytype = -1, pdstReg = 0;
    {
        const int prow = lane & 15;
        const int grow = row0 + wid * 16 + prow;
        const int ppar = lane >> 4;
        if (grow < Nn) {
            const int pd = g_perm[grow];
            { int2 a = g_offcnt[pd * RNUM + (0 + ppar)]; off_s0 = a.x; cnt_s0 = a.y; }
            { int2 a = g_offcnt[pd * RNUM + (2 + ppar)]; off_s1 = a.x; cnt_s1 = a.y; }
            { int2 a = g_offcnt[pd * RNUM + (4 + ppar)]; off_s2 = a.x; cnt_s2 = a.y; }
            if (ppar == 0) { int2 a = g_offcnt[pd * RNUM + 6]; off_s3 = a.x; cnt_s3 = a.y; }
            if (lane < 16) {
                pdstReg = pd;
                mytype = tnt[pd];
                atomicOr(&s_act[0], 1 << mytype);
            }
        }
    }
    __syncthreads();
    if (tid == 0) {
        const int m = s_act[0];
        int n = 0;
#pragma unroll
        for (int p = 0; p < RNUM; p++) s_act[2 + n++] = p;
#pragma unroll
        for (int t = 0; t < TNUM; t++)
            if (m & (1 << t)) s_act[2 + n++] = RNUM + t;
        s_act[1] = n;
    }
    __syncthreads();
    const int nact = s_act[1];

    // prefetch B phase 0
    {
        const uint4* src = g_Bf;
        const uint32_t d0 = sb + SM_B;
#pragma unroll
        for (int i = 0; i < 8; i++)
            cp16(d0 + (tid + i * 256) * 16, src + tid + i * 256);
        CP_COMMIT();
    }

    // esrc prefetch for phase 0: 8 edges per row across 4 regs.
    // esrcA: rows 0-7 j 0-3 (lane = r*4+j), esrcA2: rows 0-7 j 4-7,
    // esrcB/B2: rows 8-15.
    int esrcA, esrcB, esrcA2, esrcB2;
    {
        const int r = lane >> 2, j = lane & 3;
        int offa = __shfl_sync(0xffffffffu, off_s0, r);
        int cnta = __shfl_sync(0xffffffffu, cnt_s0, r);
        esrcA  = (j < cnta)     ? __ldg(&g_esrc[offa + j])     : 0;
        esrcA2 = (j + 4 < cnta) ? __ldg(&g_esrc[offa + j + 4]) : 0;
        int offb = __shfl_sync(0xffffffffu, off_s0, 8 + r);
        int cntb = __shfl_sync(0xffffffffu, cnt_s0, 8 + r);
        esrcB  = (j < cntb)     ? __ldg(&g_esrc[offb + j])     : 0;
        esrcB2 = (j + 4 < cntb) ? __ldg(&g_esrc[offb + j + 4]) : 0;
    }

    for (int ip = 0; ip < nact; ++ip) {
        const int phase = s_act[2 + ip];
        __syncthreads();
        if (ip + 1 < nact) {
            const uint4* src = g_Bf + (size_t)s_act[2 + ip + 1] * 2048;
            const uint32_t d0 = sb + SM_B + ((ip + 1) & 1) * BSTAGE;
#pragma unroll
            for (int i = 0; i < 8; i++)
                cp16(d0 + (tid + i * 256) * 16, src + tid + i * 256);
        }
        CP_COMMIT();

        if (phase < RNUM) {
            const int slot = phase >> 1;
            const int par = (phase & 1) * 16;
            const int offp = sel4(slot, off_s0, off_s1, off_s2, off_s3);
            const int cntp = sel4(slot, cnt_s0, cnt_s1, cnt_s2, cnt_s3);
#pragma unroll
            for (int i = 0; i < 16; i++) {
                const int cnt = __shfl_sync(0xffffffffu, cntp, par + i);
                const int off = __shfl_sync(0xffffffffu, offp, par + i);
                const int srcL = (i < 8) ? esrcA : esrcB;
                const int srcH = (i < 8) ? esrcA2 : esrcB2;
                const int ib = (i & 7) * 4;
                const int s0 = __shfl_sync(0xffffffffu, srcL, ib + 0);
                const int s1 = __shfl_sync(0xffffffffu, srcL, ib + 1);
                const int s2 = __shfl_sync(0xffffffffu, srcL, ib + 2);
                const int s3 = __shfl_sync(0xffffffffu, srcL, ib + 3);
                const int s4 = __shfl_sync(0xffffffffu, srcH, ib + 0);
                const int s5 = __shfl_sync(0xffffffffu, srcH, ib + 1);
                const int s6 = __shfl_sync(0xffffffffu, srcH, ib + 2);
                const int s7 = __shfl_sync(0xffffffffu, srcH, ib + 3);
                float4 a = make_float4(0.f, 0.f, 0.f, 0.f);
                if (cnt > 0) { float4 u = x4[(size_t)s0 * 32 + lane];
                               a.x += u.x; a.y += u.y; a.z += u.z; a.w += u.w; }
                if (cnt > 1) { float4 u = x4[(size_t)s1 * 32 + lane];
                               a.x += u.x; a.y += u.y; a.z += u.z; a.w += u.w; }
                if (cnt > 2) { float4 u = x4[(size_t)s2 * 32 + lane];
                               a.x += u.x; a.y += u.y; a.z += u.z; a.w += u.w; }
                if (cnt > 3) { float4 u = x4[(size_t)s3 * 32 + lane];
                               a.x += u.x; a.y += u.y; a.z += u.z; a.w += u.w; }
                if (cnt > 4) { float4 u = x4[(size_t)s4 * 32 + lane];
                               a.x += u.x; a.y += u.y; a.z += u.z; a.w += u.w; }
                if (cnt > 5) { float4 u = x4[(size_t)s5 * 32 + lane];
                               a.x += u.x; a.y += u.y; a.z += u.z; a.w += u.w; }
                if (cnt > 6) { float4 u = x4[(size_t)s6 * 32 + lane];
                               a.x += u.x; a.y += u.y; a.z += u.z; a.w += u.w; }
                if (cnt > 7) { float4 u = x4[(size_t)s7 * 32 + lane];
                               a.x += u.x; a.y += u.y; a.z += u.z; a.w += u.w; }
                for (int j = 8; j < cnt; j++) {          // extremely rare
                    float4 u = x4[(size_t)__ldg(&g_esrc[off + j]) * 32 + lane];
                    a.x += u.x; a.y += u.y; a.z += u.z; a.w += u.w;
                }
                const float inv = 1.f / fmaxf((float)cnt, 1.f);
                a.x *= inv; a.y *= inv; a.z *= inv; a.w *= inv;
                storeA(sb, wid * 16 + i, lane, a);
            }
        } else {
            const int t = phase - RNUM;
#pragma unroll
            for (int i = 0; i < 16; i++) {
                const int ty = __shfl_sync(0xffffffffu, mytype, i);
                const int pdst = __shfl_sync(0xffffffffu, pdstReg, i);
                float4 v = make_float4(0.f, 0.f, 0.f, 0.f);
                if (ty == t) v = x4[(size_t)pdst * 32 + lane];
                storeA(sb, wid * 16 + i, lane, v);
            }
        }
        if (phase + 1 < RNUM) {
            const int np = phase + 1;
            const int slot = np >> 1;
            const int par = (np & 1) * 16;
            const int offp = sel4(slot, off_s0, off_s1, off_s2, off_s3);
            const int cntp = sel4(slot, cnt_s0, cnt_s1, cnt_s2, cnt_s3);
            const int r = lane >> 2, j = lane & 3;
            int offa = __shfl_sync(0xffffffffu, offp, par + r);
            int cnta = __shfl_sync(0xffffffffu, cntp, par + r);
            esrcA  = (j < cnta)     ? __ldg(&g_esrc[offa + j])     : 0;
            esrcA2 = (j + 4 < cnta) ? __ldg(&g_esrc[offa + j + 4]) : 0;
            int offb = __shfl_sync(0xffffffffu, offp, par + 8 + r);
            int cntb = __shfl_sync(0xffffffffu, cntp, par + 8 + r);
            esrcB  = (j < cntb)     ? __ldg(&g_esrc[offb + j])     : 0;
            esrcB2 = (j + 4 < cntb) ? __ldg(&g_esrc[offb + j + 4]) : 0;
        }

        CP_WAIT1();
        __syncthreads();
        const uint32_t sbB = sb + SM_B + (ip & 1) * BSTAGE;
#pragma unroll
        for (int cc = 0; cc < 2; cc++) {
#pragma unroll
            for (int s = 0; s < 4; s++) {
                uint32_t ah0[4], ah1[4];
                const uint32_t ab0 = sb + cc * ATB + (uint32_t)wm0 * SROW + s * 32 + a_roff;
                ldmat_x4(ab0, ah0);
                ldmat_x4(ab0 + 16 * SROW, ah1);
#pragma unroll
                for (int jp = 0; jp < 4; jp++) {
                    const uint32_t boff = sbB +
                        ((uint32_t)cc * 1024 + ((jbase + jp) * 4 + s) * 32 + lane) * 16;
                    uint4 BH = lds128(boff);
                    mma4(acc[2 * jp],         ah0, BH.x, BH.y);
                    mma4(acc[2 * jp + 1],     ah0, BH.z, BH.w);
                    mma4(acc[8 + 2 * jp],     ah1, BH.x, BH.y);
                    mma4(acc[8 + 2 * jp + 1], ah1, BH.z, BH.w);
                }
            }
        }
    }

    // ---- epilogue ----
    const int g = lane >> 2, tig = lane & 3;
#pragma unroll
    for (int ms = 0; ms < 2; ms++) {
        const int gr1 = row0 + wm0 + ms * 16 + g;
        const int gr2 = gr1 + 8;
        const int n1 = (gr1 < Nn) ? g_perm[gr1] : 0;
        const int n2 = (gr2 < Nn) ? g_perm[gr2] : 0;
        const int t1 = (gr1 < Nn) ? tnt[n1] : 0;
        const int t2 = (gr2 < Nn) ? tnt[n2] : 0;
#pragma unroll
        for (int nt = 0; nt < 8; nt++) {
            const int col = wn0 + nt * 8 + tig * 2;
            if (gr1 < Nn) {
                float2 b1 = *reinterpret_cast<const float2*>(root_b + t1 * CDIM + col);
                *reinterpret_cast<float2*>(out + (size_t)n1 * CDIM + col) =
                    make_float2(acc[ms * 8 + nt][0] + b1.x, acc[ms * 8 + nt][1] + b1.y);
            }
            if (gr2 < Nn) {
                float2 b2 = *reinterpret_cast<const float2*>(root_b + t2 * CDIM + col);
                *reinterpret_cast<float2*>(out + (size_t)n2 * CDIM + col) =
                    make_float2(acc[ms * 8 + nt][2] + b2.x, acc[ms * 8 + nt][3] + b2.y);
            }
        }
    }
}

// ---------------------------------------------------------------------------
extern "C" void kernel_launch(void* const* d_in, const int* in_sizes, int n_in,
                              void* d_out, int out_size) {
    const float* x      = (const float*)d_in[0];
    const int*   ei     = (const int*)d_in[1];
    const int*   et     = (const int*)d_in[2];
    const int*   tnt    = (const int*)d_in[3];
    const float* rel_w  = (const float*)d_in[4];
    const float* root_w = (const float*)d_in[5];
    const float* root_b = (const float*)d_in[6];
    float* out = (float*)d_out;

    int E  = in_sizes[2];
    int Nn = in_sizes[3];
    int nseg = Nn * RNUM;
    int nb = (nseg + 1023) / 1024;
    int eb = (E + 255) / 256;
    int tb = (Nn + 255) / 256;
    int bfb = (NCHK * 8 * 4 * 32 + 255) / 256;
    int cg = ((E > Nn ? E : Nn) + 255) / 256;

    cudaFuncSetAttribute(k_fused, cudaFuncAttributeMaxDynamicSharedMemorySize, SM_TOT);

    k_count_t<<<cg, 256>>>(ei, et, tnt, E, Nn);
    k_scan1b<<<nb + bfb, 256>>>(nseg, nb, rel_w, root_w);
    k_scan2t<<<1, 1024>>>(nb);
    k_scan3z<<<(nseg + 255) / 256, 256>>>(nseg);
    k_scatter2<<<eb + tb, 256>>>(ei, et, tnt, E, Nn, eb);
    k_fused<<<(Nn + 127) / 128, 256, SM_TOT>>>(x, tnt, root_b, out, Nn);
}

// round 15
// speedup vs baseline: 1.0775x; 1.0775x over previous
#include <cuda_runtime.h>
#include <cuda_fp16.h>
#include <cstdint>

#define CDIM 128
#define RNUM 7
#define TNUM 4
#define MAXN 100000
#define MAXE 2000000
#define NPH  (RNUM + TNUM)
#define NCHK 22
#define SROW 144
#define ATB  (128 * SROW)
#define SM_B (2 * ATB)
#define BSTAGE 32768
#define SM_ACT (SM_B + 2 * BSTAGE)
#define SM_TOT (SM_ACT + 64)

// ---------------- device scratch (zero at graph entry — invariant maintained
// by re-zeroing counters after their last read inside each graph execution) --
__device__ int  g_cnt[MAXN * RNUM];
__device__ int  g_off[MAXN * RNUM];
__device__ int  g_cur[MAXN * RNUM];
__device__ int2 g_offcnt[MAXN * RNUM];
__device__ int  g_bsum[1024];
__device__ int  g_esrc[MAXE];
__device__ int  g_tcnt[4], g_tcur[4];
__device__ int  g_perm[MAXN];
__device__ __align__(16) uint32_t g_xh[(size_t)MAXN * 64];   // fp16 copy of x
__device__ __align__(16) uint4 g_Bf[NCHK * 8 * 4 * 32];

// ---------------- helpers ----------------
__device__ __forceinline__ uint32_t smem_u32(const void* p) {
    uint32_t a;
    asm("{ .reg .u64 t; cvta.to.shared.u64 t, %1; cvt.u32.u64 %0, t; }" : "=r"(a) : "l"(p));
    return a;
}
__device__ __forceinline__ void ldmat_x4(uint32_t addr, uint32_t* r) {
    asm volatile("ldmatrix.sync.aligned.m8n8.x4.shared.b16 {%0,%1,%2,%3}, [%4];"
                 : "=r"(r[0]), "=r"(r[1]), "=r"(r[2]), "=r"(r[3]) : "r"(addr));
}
__device__ __forceinline__ void mma4(float* d, const uint32_t* a, uint32_t b0, uint32_t b1) {
    asm volatile("mma.sync.aligned.m16n8k16.row.col.f32.f16.f16.f32 "
                 "{%0,%1,%2,%3}, {%4,%5,%6,%7}, {%8,%9}, {%0,%1,%2,%3};"
                 : "+f"(d[0]), "+f"(d[1]), "+f"(d[2]), "+f"(d[3])
                 : "r"(a[0]), "r"(a[1]), "r"(a[2]), "r"(a[3]), "r"(b0), "r"(b1));
}
__device__ __forceinline__ uint32_t packh(float a, float b) {
    __half2 h = __floats2half2_rn(a, b);
    return *reinterpret_cast<uint32_t*>(&h);
}
__device__ __forceinline__ uint4 lds128(uint32_t addr) {
    uint4 v;
    asm volatile("ld.shared.v4.b32 {%0,%1,%2,%3}, [%4];"
                 : "=r"(v.x), "=r"(v.y), "=r"(v.z), "=r"(v.w) : "r"(addr));
    return v;
}
__device__ __forceinline__ void cp16(uint32_t s, const void* g) {
    asm volatile("cp.async.cg.shared.global [%0], [%1], 16;" :: "r"(s), "l"(g));
}
#define CP_COMMIT() asm volatile("cp.async.commit_group;" ::: "memory")
#define CP_WAIT1()  asm volatile("cp.async.wait_group 1;" ::: "memory")

__device__ __forceinline__ int sel4(int s, int a0, int a1, int a2, int a3) {
    int lo = (s & 1) ? a1 : a0;
    int hi = (s & 1) ? a3 : a2;
    return (s & 2) ? hi : lo;
}
// accumulate one edge's 4 fp16 channels (uint2) into half2 accumulators
__device__ __forceinline__ void hacc(__half2& a01, __half2& a23, uint2 u) {
    a01 = __hadd2(a01, *reinterpret_cast<__half2*>(&u.x));
    a23 = __hadd2(a23, *reinterpret_cast<__half2*>(&u.y));
}
// store the fp16 A fragment (4 channels) of row m
__device__ __forceinline__ void storeA16(uint32_t sbase, int m, int lane,
                                         __half2 a01, __half2 a23) {
    int chunk = lane >> 4;
    uint32_t boff = (uint32_t)m * SROW + (lane & 15) * 8;
    uint32_t r0 = *reinterpret_cast<uint32_t*>(&a01);
    uint32_t r1 = *reinterpret_cast<uint32_t*>(&a23);
    asm volatile("st.shared.v2.b32 [%0], {%1,%2};"
                 :: "r"(sbase + chunk * ATB + boff), "r"(r0), "r"(r1) : "memory");
}

// ---------------- prologue (5 launches) ----------------
// 1: edge histogram + node-type histogram + fp16 x conversion
__global__ void k_count_t(const int* __restrict__ ei, const int* __restrict__ et,
                          const int* __restrict__ tnt, const float* __restrict__ x,
                          int E, int Nn) {
    __shared__ int h[4];
    if (threadIdx.x < 4) h[threadIdx.x] = 0;
    __syncthreads();
    int i = blockIdx.x * blockDim.x + threadIdx.x;
    if (i < E) atomicAdd(&g_cnt[ei[E + i] * RNUM + et[i]], 1);
    if (i < Nn) atomicAdd(&h[tnt[i]], 1);
    // fp16 conversion: thread i handles uint32s [4i, 4i+4) = floats [8i, 8i+8)
    int xi = i * 4;
    if (xi < Nn * 64) {
        const float4* x4 = reinterpret_cast<const float4*>(x);
        float4 fa = x4[xi >> 1];
        float4 fb = x4[(xi >> 1) + 1];
        uint4 o;
        o.x = packh(fa.x, fa.y); o.y = packh(fa.z, fa.w);
        o.z = packh(fb.x, fb.y); o.w = packh(fb.z, fb.w);
        *reinterpret_cast<uint4*>(&g_xh[xi]) = o;
    }
    __syncthreads();
    if (threadIdx.x < 4 && h[threadIdx.x]) atomicAdd(&g_tcnt[threadIdx.x], h[threadIdx.x]);
}
// 2: block-level scan (blocks [0,nb)) + B fragment build (blocks [nb, nb+88))
__global__ void k_scan1b(int nseg, int nb,
                         const float* __restrict__ rel_w,
                         const float* __restrict__ root_w) {
    if ((int)blockIdx.x >= nb) {
        int idx = ((int)blockIdx.x - nb) * 256 + threadIdx.x;
        if (idx >= NCHK * 8 * 4 * 32) return;
        int lane = idx & 31;
        int s = (idx >> 5) & 3;
        int j = (idx >> 7) & 7;
        int chunk = idx >> 10;
        uint32_t hq[4];
#pragma unroll
        for (int q = 0; q < 4; q++) {
            int n = j * 16 + ((q & 2) ? 8 : 0) + (lane >> 2);
            int kk = s * 16 + ((q & 1) ? 8 : 0) + 2 * (lane & 3);
            float w0, w1;
            if (chunk < 14) {
                int r = chunk >> 1, kb = (chunk & 1) * 64;
                const float* p = rel_w + ((size_t)(r * CDIM + n)) * CDIM + kb + kk;
                w0 = p[0]; w1 = p[1];
            } else {
                int rc = chunk - 14;
                int t = rc >> 1, kb = (rc & 1) * 64;
                const float* p = root_w + ((size_t)(t * CDIM + n)) * CDIM + kb + kk;
                w0 = p[0]; w1 = p[1];
            }
            hq[q] = packh(w0, w1);
        }
        g_Bf[(((size_t)chunk * 8 + j) * 4 + s) * 32 + lane] =
            make_uint4(hq[0], hq[1], hq[2], hq[3]);
        return;
    }
    __shared__ int wsum[8];
    int tid = threadIdx.x;
    int base = blockIdx.x * 1024 + tid * 4;
    int v0 = 0, v1 = 0, v2 = 0, v3 = 0;
    if (base + 0 < nseg) v0 = g_cnt[base + 0];
    if (base + 1 < nseg) v1 = g_cnt[base + 1];
    if (base + 2 < nseg) v2 = g_cnt[base + 2];
    if (base + 3 < nseg) v3 = g_cnt[base + 3];
    int tot = v0 + v1 + v2 + v3;
    int lane = tid & 31, wid = tid >> 5;
    int inc = tot;
#pragma unroll
    for (int d = 1; d < 32; d <<= 1) {
        int t = __shfl_up_sync(0xffffffff, inc, d);
        if (lane >= d) inc += t;
    }
    if (lane == 31) wsum[wid] = inc;
    __syncthreads();
    if (wid == 0) {
        int w = (lane < 8) ? wsum[lane] : 0;
#pragma unroll
        for (int d = 1; d < 8; d <<= 1) {
            int t = __shfl_up_sync(0xffffffff, w, d);
            if (lane >= d) w += t;
        }
        if (lane < 8) wsum[lane] = w;
    }
    __syncthreads();
    int excl = inc - tot + (wid ? wsum[wid - 1] : 0);
    if (base + 0 < nseg) g_off[base + 0] = excl;
    if (base + 1 < nseg) g_off[base + 1] = excl + v0;
    if (base + 2 < nseg) g_off[base + 2] = excl + v0 + v1;
    if (base + 3 < nseg) g_off[base + 3] = excl + v0 + v1 + v2;
    if (tid == 255) g_bsum[blockIdx.x] = wsum[7];
}
__global__ void k_scan2t(int nb) {
    __shared__ int sm[1024];
    int tid = threadIdx.x;
    int v = (tid < nb) ? g_bsum[tid] : 0;
    sm[tid] = v;
    __syncthreads();
    for (int d = 1; d < 1024; d <<= 1) {
        int t = (tid >= d) ? sm[tid - d] : 0;
        __syncthreads();
        sm[tid] += t;
        __syncthreads();
    }
    if (tid < nb) g_bsum[tid] = sm[tid] - v;
    if (tid == 0) {
        int a = g_tcnt[0], b = g_tcnt[1], c = g_tcnt[2];
        g_tcur[0] = 0; g_tcur[1] = a; g_tcur[2] = a + b; g_tcur[3] = a + b + c;
        g_tcnt[0] = 0; g_tcnt[1] = 0; g_tcnt[2] = 0; g_tcnt[3] = 0;
    }
}
__global__ void k_scan3z(int nseg) {
    int i = blockIdx.x * blockDim.x + threadIdx.x;
    if (i < nseg) {
        int v = g_off[i] + g_bsum[i >> 10];
        g_cur[i] = v;
        g_offcnt[i] = make_int2(v, g_cnt[i]);
        g_cnt[i] = 0;
    }
}
__global__ void k_scatter2(const int* __restrict__ ei, const int* __restrict__ et,
                           const int* __restrict__ tnt, int E, int Nn, int eb) {
    if ((int)blockIdx.x < eb) {
        int e = blockIdx.x * 256 + threadIdx.x;
        if (e < E) {
            int s = ei[E + e] * RNUM + et[e];
            int p = atomicAdd(&g_cur[s], 1);
            g_esrc[p] = ei[e];
        }
        return;
    }
    __shared__ int loc[4], base[4];
    if (threadIdx.x < 4) loc[threadIdx.x] = 0;
    __syncthreads();
    int i = ((int)blockIdx.x - eb) * 256 + threadIdx.x;
    int t = 0, my = 0;
    bool ok = (i < Nn);
    if (ok) { t = tnt[i]; my = atomicAdd(&loc[t], 1); }
    __syncthreads();
    if (threadIdx.x < 4) base[threadIdx.x] = atomicAdd(&g_tcur[threadIdx.x], loc[threadIdx.x]);
    __syncthreads();
    if (ok) g_perm[base[t] + my] = i;
}

// ---------------- fused: 256 threads, 2 CTAs/SM, half2-native gather --------
__global__ __launch_bounds__(256, 2) void k_fused(const int* __restrict__ tnt,
                                                  const float* __restrict__ root_b,
                                                  float* __restrict__ out, int Nn) {
    extern __shared__ char smem[];
    const uint32_t sb = smem_u32(smem);
    int* s_act = reinterpret_cast<int*>(smem + SM_ACT);
    const int tid = threadIdx.x, wid = tid >> 5, lane = tid & 31;
    const int row0 = blockIdx.x * 128;
    const int wm0 = (wid & 3) * 32;
    const int jbase = (wid >> 2) * 4;
    const int wn0 = jbase * 16;
    const int quad = lane >> 3, lrow = lane & 7;
    const int a_roff = ((quad & 1) * 8 + lrow) * SROW + ((quad >> 1) * 8) * 2;
    const uint2* xh2 = reinterpret_cast<const uint2*>(g_xh);

    float acc[16][4];
#pragma unroll
    for (int j = 0; j < 16; j++)
#pragma unroll
        for (int q = 0; q < 4; q++) acc[j][q] = 0.f;

    if (tid == 0) s_act[0] = 0;
    __syncthreads();

    int off_s0 = 0, cnt_s0 = 0, off_s1 = 0, cnt_s1 = 0;
    int off_s2 = 0, cnt_s2 = 0, off_s3 = 0, cnt_s3 = 0;
    int mytype = -1, pdstReg = 0;
    {
        const int prow = lane & 15;
        const int grow = row0 + wid * 16 + prow;
        const int ppar = lane >> 4;
        if (grow < Nn) {
            const int pd = g_perm[grow];
            { int2 a = g_offcnt[pd * RNUM + (0 + ppar)]; off_s0 = a.x; cnt_s0 = a.y; }
            { int2 a = g_offcnt[pd * RNUM + (2 + ppar)]; off_s1 = a.x; cnt_s1 = a.y; }
            { int2 a = g_offcnt[pd * RNUM + (4 + ppar)]; off_s2 = a.x; cnt_s2 = a.y; }
            if (ppar == 0) { int2 a = g_offcnt[pd * RNUM + 6]; off_s3 = a.x; cnt_s3 = a.y; }
            if (lane < 16) {
                pdstReg = pd;
                mytype = tnt[pd];
                atomicOr(&s_act[0], 1 << mytype);
            }
        }
    }
    __syncthreads();
    if (tid == 0) {
        const int m = s_act[0];
        int n = 0;
#pragma unroll
        for (int p = 0; p < RNUM; p++) s_act[2 + n++] = p;
#pragma unroll
        for (int t = 0; t < TNUM; t++)
            if (m & (1 << t)) s_act[2 + n++] = RNUM + t;
        s_act[1] = n;
    }
    __syncthreads();
    const int nact = s_act[1];

    // prefetch B phase 0
    {
        const uint4* src = g_Bf;
        const uint32_t d0 = sb + SM_B;
#pragma unroll
        for (int i = 0; i < 8; i++)
            cp16(d0 + (tid + i * 256) * 16, src + tid + i * 256);
        CP_COMMIT();
    }

    // esrc prefetch for phase 0 (4 edges per row)
    int esrcA, esrcB;
    {
        const int r = lane >> 2, j = lane & 3;
        int offa = __shfl_sync(0xffffffffu, off_s0, r);
        int cnta = __shfl_sync(0xffffffffu, cnt_s0, r);
        esrcA = (j < cnta) ? __ldg(&g_esrc[offa + j]) : 0;
        int offb = __shfl_sync(0xffffffffu, off_s0, 8 + r);
        int cntb = __shfl_sync(0xffffffffu, cnt_s0, 8 + r);
        esrcB = (j < cntb) ? __ldg(&g_esrc[offb + j]) : 0;
    }

    for (int ip = 0; ip < nact; ++ip) {
        const int phase = s_act[2 + ip];
        __syncthreads();
        if (ip + 1 < nact) {
            const uint4* src = g_Bf + (size_t)s_act[2 + ip + 1] * 2048;
            const uint32_t d0 = sb + SM_B + ((ip + 1) & 1) * BSTAGE;
#pragma unroll
            for (int i = 0; i < 8; i++)
                cp16(d0 + (tid + i * 256) * 16, src + tid + i * 256);
        }
        CP_COMMIT();

        if (phase < RNUM) {
            const int slot = phase >> 1;
            const int par = (phase & 1) * 16;
            const int offp = sel4(slot, off_s0, off_s1, off_s2, off_s3);
            const int cntp = sel4(slot, cnt_s0, cnt_s1, cnt_s2, cnt_s3);
#pragma unroll
            for (int i = 0; i < 16; i++) {
                const int cnt = __shfl_sync(0xffffffffu, cntp, par + i);
                const int off = __shfl_sync(0xffffffffu, offp, par + i);
                const int src01 = (i < 8) ? esrcA : esrcB;
                const int ib = (i & 7) * 4;
                const int s0 = __shfl_sync(0xffffffffu, src01, ib + 0);
                const int s1 = __shfl_sync(0xffffffffu, src01, ib + 1);
                const int s2 = __shfl_sync(0xffffffffu, src01, ib + 2);
                const int s3 = __shfl_sync(0xffffffffu, src01, ib + 3);
                __half2 a01 = __float2half2_rn(0.f), a23 = a01;
                if (cnt > 0) hacc(a01, a23, xh2[(size_t)s0 * 32 + lane]);
                if (cnt > 1) hacc(a01, a23, xh2[(size_t)s1 * 32 + lane]);
                if (cnt > 2) hacc(a01, a23, xh2[(size_t)s2 * 32 + lane]);
                if (cnt > 3) hacc(a01, a23, xh2[(size_t)s3 * 32 + lane]);
                for (int j = 4; j < cnt; j++)
                    hacc(a01, a23, xh2[(size_t)__ldg(&g_esrc[off + j]) * 32 + lane]);
                if (cnt > 1) {
                    __half2 hv = __float2half2_rn(1.f / (float)cnt);
                    a01 = __hmul2(a01, hv);
                    a23 = __hmul2(a23, hv);
                }
                storeA16(sb, wid * 16 + i, lane, a01, a23);
            }
        } else {
            const int t = phase - RNUM;
#pragma unroll
            for (int i = 0; i < 16; i++) {
                const int ty = __shfl_sync(0xffffffffu, mytype, i);
                const int pdst = __shfl_sync(0xffffffffu, pdstReg, i);
                __half2 a01 = __float2half2_rn(0.f), a23 = a01;
                if (ty == t) hacc(a01, a23, xh2[(size_t)pdst * 32 + lane]);
                storeA16(sb, wid * 16 + i, lane, a01, a23);
            }
        }
        if (phase + 1 < RNUM) {
            const int np = phase + 1;
            const int slot = np >> 1;
            const int par = (np & 1) * 16;
            const int offp = sel4(slot, off_s0, off_s1, off_s2, off_s3);
            const int cntp = sel4(slot, cnt_s0, cnt_s1, cnt_s2, cnt_s3);
            const int r = lane >> 2, j = lane & 3;
            int offa = __shfl_sync(0xffffffffu, offp, par + r);
            int cnta = __shfl_sync(0xffffffffu, cntp, par + r);
            esrcA = (j < cnta) ? __ldg(&g_esrc[offa + j]) : 0;
            int offb = __shfl_sync(0xffffffffu, offp, par + 8 + r);
            int cntb = __shfl_sync(0xffffffffu, cntp, par + 8 + r);
            esrcB = (j < cntb) ? __ldg(&g_esrc[offb + j]) : 0;
        }

        CP_WAIT1();
        __syncthreads();
        const uint32_t sbB = sb + SM_B + (ip & 1) * BSTAGE;
#pragma unroll
        for (int cc = 0; cc < 2; cc++) {
#pragma unroll
            for (int s = 0; s < 4; s++) {
                uint32_t ah0[4], ah1[4];
                const uint32_t ab0 = sb + cc * ATB + (uint32_t)wm0 * SROW + s * 32 + a_roff;
                ldmat_x4(ab0, ah0);
                ldmat_x4(ab0 + 16 * SROW, ah1);
#pragma unroll
                for (int jp = 0; jp < 4; jp++) {
                    const uint32_t boff = sbB +
                        ((uint32_t)cc * 1024 + ((jbase + jp) * 4 + s) * 32 + lane) * 16;
                    uint4 BH = lds128(boff);
                    mma4(acc[2 * jp],         ah0, BH.x, BH.y);
                    mma4(acc[2 * jp + 1],     ah0, BH.z, BH.w);
                    mma4(acc[8 + 2 * jp],     ah1, BH.x, BH.y);
                    mma4(acc[8 + 2 * jp + 1], ah1, BH.z, BH.w);
                }
            }
        }
    }

    // ---- epilogue ----
    const int g = lane >> 2, tig = lane & 3;
#pragma unroll
    for (int ms = 0; ms < 2; ms++) {
        const int gr1 = row0 + wm0 + ms * 16 + g;
        const int gr2 = gr1 + 8;
        const int n1 = (gr1 < Nn) ? g_perm[gr1] : 0;
        const int n2 = (gr2 < Nn) ? g_perm[gr2] : 0;
        const int t1 = (gr1 < Nn) ? tnt[n1] : 0;
        const int t2 = (gr2 < Nn) ? tnt[n2] : 0;
#pragma unroll
        for (int nt = 0; nt < 8; nt++) {
            const int col = wn0 + nt * 8 + tig * 2;
            if (gr1 < Nn) {
                float2 b1 = *reinterpret_cast<const float2*>(root_b + t1 * CDIM + col);
                *reinterpret_cast<float2*>(out + (size_t)n1 * CDIM + col) =
                    make_float2(acc[ms * 8 + nt][0] + b1.x, acc[ms * 8 + nt][1] + b1.y);
            }
            if (gr2 < Nn) {
                float2 b2 = *reinterpret_cast<const float2*>(root_b + t2 * CDIM + col);
                *reinterpret_cast<float2*>(out + (size_t)n2 * CDIM + col) =
                    make_float2(acc[ms * 8 + nt][2] + b2.x, acc[ms * 8 + nt][3] + b2.y);
            }
        }
    }
}

// ---------------------------------------------------------------------------
extern "C" void kernel_launch(void* const* d_in, const int* in_sizes, int n_in,
                              void* d_out, int out_size) {
    const float* x      = (const float*)d_in[0];
    const int*   ei     = (const int*)d_in[1];
    const int*   et     = (const int*)d_in[2];
    const int*   tnt    = (const int*)d_in[3];
    const float* rel_w  = (const float*)d_in[4];
    const float* root_w = (const float*)d_in[5];
    const float* root_b = (const float*)d_in[6];
    float* out = (float*)d_out;

    int E  = in_sizes[2];
    int Nn = in_sizes[3];
    int nseg = Nn * RNUM;
    int nb = (nseg + 1023) / 1024;
    int eb = (E + 255) / 256;
    int tb = (Nn + 255) / 256;
    int bfb = (NCHK * 8 * 4 * 32 + 255) / 256;
    int xw = Nn * 16;                      // threads needed for fp16 conversion
    int cgmax = E > Nn ? E : Nn;
    if (xw > cgmax) cgmax = xw;
    int cg = (cgmax + 255) / 256;

    cudaFuncSetAttribute(k_fused, cudaFuncAttributeMaxDynamicSharedMemorySize, SM_TOT);

    k_count_t<<<cg, 256>>>(ei, et, tnt, x, E, Nn);
    k_scan1b<<<nb + bfb, 256>>>(nseg, nb, rel_w, root_w);
    k_scan2t<<<1, 1024>>>(nb);
    k_scan3z<<<(nseg + 255) / 256, 256>>>(nseg);
    k_scatter2<<<eb + tb, 256>>>(ei, et, tnt, E, Nn, eb);
    k_fused<<<(Nn + 127) / 128, 256, SM_TOT>>>(tnt, root_b, out, Nn);
}

// round 16
// speedup vs baseline: 1.0777x; 1.0002x over previous
#include <cuda_runtime.h>
#include <cuda_fp16.h>
#include <cstdint>

#define CDIM 128
#define RNUM 7
#define TNUM 4
#define MAXN 100000
#define MAXE 2000000
#define NPH  (RNUM + TNUM)
#define NCHK 22
#define SROW 144
#define ATB  (128 * SROW)
#define SM_B (2 * ATB)
#define BSTAGE 32768
#define SM_ACT (SM_B + 2 * BSTAGE)
#define SM_TOT (SM_ACT + 96)

// ---------------- device scratch (zero at graph entry — invariant maintained
// by re-zeroing counters after their last read inside each graph execution) --
__device__ int  g_cnt[MAXN * RNUM];
__device__ int  g_off[MAXN * RNUM];
__device__ int  g_cur[MAXN * RNUM];
__device__ int2 g_offcnt[MAXN * RNUM];
__device__ int  g_bsum[1024];
__device__ int  g_esrc[MAXE];
__device__ int  g_tcnt[4], g_tcur[4];
__device__ int  g_perm[MAXN];
__device__ int  g_ticket;                                    // reset by k_scan2t
__device__ __align__(16) uint32_t g_xh[(size_t)MAXN * 64];   // fp16 copy of x
__device__ __align__(16) uint4 g_Bf[NCHK * 8 * 4 * 32];

// ---------------- helpers ----------------
__device__ __forceinline__ uint32_t smem_u32(const void* p) {
    uint32_t a;
    asm("{ .reg .u64 t; cvta.to.shared.u64 t, %1; cvt.u32.u64 %0, t; }" : "=r"(a) : "l"(p));
    return a;
}
__device__ __forceinline__ void ldmat_x4(uint32_t addr, uint32_t* r) {
    asm volatile("ldmatrix.sync.aligned.m8n8.x4.shared.b16 {%0,%1,%2,%3}, [%4];"
                 : "=r"(r[0]), "=r"(r[1]), "=r"(r[2]), "=r"(r[3]) : "r"(addr));
}
__device__ __forceinline__ void mma4(float* d, const uint32_t* a, uint32_t b0, uint32_t b1) {
    asm volatile("mma.sync.aligned.m16n8k16.row.col.f32.f16.f16.f32 "
                 "{%0,%1,%2,%3}, {%4,%5,%6,%7}, {%8,%9}, {%0,%1,%2,%3};"
                 : "+f"(d[0]), "+f"(d[1]), "+f"(d[2]), "+f"(d[3])
                 : "r"(a[0]), "r"(a[1]), "r"(a[2]), "r"(a[3]), "r"(b0), "r"(b1));
}
__device__ __forceinline__ uint32_t packh(float a, float b) {
    __half2 h = __floats2half2_rn(a, b);
    return *reinterpret_cast<uint32_t*>(&h);
}
__device__ __forceinline__ uint4 lds128(uint32_t addr) {
    uint4 v;
    asm volatile("ld.shared.v4.b32 {%0,%1,%2,%3}, [%4];"
                 : "=r"(v.x), "=r"(v.y), "=r"(v.z), "=r"(v.w) : "r"(addr));
    return v;
}
__device__ __forceinline__ void cp16(uint32_t s, const void* g) {
    asm volatile("cp.async.cg.shared.global [%0], [%1], 16;" :: "r"(s), "l"(g));
}
#define CP_COMMIT() asm volatile("cp.async.commit_group;" ::: "memory")
#define CP_WAIT1()  asm volatile("cp.async.wait_group 1;" ::: "memory")
#define CP_WAIT0()  asm volatile("cp.async.wait_group 0;" ::: "memory")

__device__ __forceinline__ int sel4(int s, int a0, int a1, int a2, int a3) {
    int lo = (s & 1) ? a1 : a0;
    int hi = (s & 1) ? a3 : a2;
    return (s & 2) ? hi : lo;
}
__device__ __forceinline__ void hacc(__half2& a01, __half2& a23, uint2 u) {
    a01 = __hadd2(a01, *reinterpret_cast<__half2*>(&u.x));
    a23 = __hadd2(a23, *reinterpret_cast<__half2*>(&u.y));
}
__device__ __forceinline__ void storeA16(uint32_t sbase, int m, int lane,
                                         __half2 a01, __half2 a23) {
    int chunk = lane >> 4;
    uint32_t boff = (uint32_t)m * SROW + (lane & 15) * 8;
    uint32_t r0 = *reinterpret_cast<uint32_t*>(&a01);
    uint32_t r1 = *reinterpret_cast<uint32_t*>(&a23);
    asm volatile("st.shared.v2.b32 [%0], {%1,%2};"
                 :: "r"(sbase + chunk * ATB + boff), "r"(r0), "r"(r1) : "memory");
}

// ---------------- prologue (5 launches) ----------------
__global__ void k_count_t(const int* __restrict__ ei, const int* __restrict__ et,
                          const int* __restrict__ tnt, const float* __restrict__ x,
                          int E, int Nn) {
    __shared__ int h[4];
    if (threadIdx.x < 4) h[threadIdx.x] = 0;
    __syncthreads();
    int i = blockIdx.x * blockDim.x + threadIdx.x;
    if (i < E) atomicAdd(&g_cnt[ei[E + i] * RNUM + et[i]], 1);
    if (i < Nn) atomicAdd(&h[tnt[i]], 1);
    int xi = i * 4;
    if (xi < Nn * 64) {
        const float4* x4 = reinterpret_cast<const float4*>(x);
        float4 fa = x4[xi >> 1];
        float4 fb = x4[(xi >> 1) + 1];
        uint4 o;
        o.x = packh(fa.x, fa.y); o.y = packh(fa.z, fa.w);
        o.z = packh(fb.x, fb.y); o.w = packh(fb.z, fb.w);
        *reinterpret_cast<uint4*>(&g_xh[xi]) = o;
    }
    __syncthreads();
    if (threadIdx.x < 4 && h[threadIdx.x]) atomicAdd(&g_tcnt[threadIdx.x], h[threadIdx.x]);
}
__global__ void k_scan1b(int nseg, int nb,
                         const float* __restrict__ rel_w,
                         const float* __restrict__ root_w) {
    if ((int)blockIdx.x >= nb) {
        int idx = ((int)blockIdx.x - nb) * 256 + threadIdx.x;
        if (idx >= NCHK * 8 * 4 * 32) return;
        int lane = idx & 31;
        int s = (idx >> 5) & 3;
        int j = (idx >> 7) & 7;
        int chunk = idx >> 10;
        uint32_t hq[4];
#pragma unroll
        for (int q = 0; q < 4; q++) {
            int n = j * 16 + ((q & 2) ? 8 : 0) + (lane >> 2);
            int kk = s * 16 + ((q & 1) ? 8 : 0) + 2 * (lane & 3);
            float w0, w1;
            if (chunk < 14) {
                int r = chunk >> 1, kb = (chunk & 1) * 64;
                const float* p = rel_w + ((size_t)(r * CDIM + n)) * CDIM + kb + kk;
                w0 = p[0]; w1 = p[1];
            } else {
                int rc = chunk - 14;
                int t = rc >> 1, kb = (rc & 1) * 64;
                const float* p = root_w + ((size_t)(t * CDIM + n)) * CDIM + kb + kk;
                w0 = p[0]; w1 = p[1];
            }
            hq[q] = packh(w0, w1);
        }
        g_Bf[(((size_t)chunk * 8 + j) * 4 + s) * 32 + lane] =
            make_uint4(hq[0], hq[1], hq[2], hq[3]);
        return;
    }
    __shared__ int wsum[8];
    int tid = threadIdx.x;
    int base = blockIdx.x * 1024 + tid * 4;
    int v0 = 0, v1 = 0, v2 = 0, v3 = 0;
    if (base + 0 < nseg) v0 = g_cnt[base + 0];
    if (base + 1 < nseg) v1 = g_cnt[base + 1];
    if (base + 2 < nseg) v2 = g_cnt[base + 2];
    if (base + 3 < nseg) v3 = g_cnt[base + 3];
    int tot = v0 + v1 + v2 + v3;
    int lane = tid & 31, wid = tid >> 5;
    int inc = tot;
#pragma unroll
    for (int d = 1; d < 32; d <<= 1) {
        int t = __shfl_up_sync(0xffffffff, inc, d);
        if (lane >= d) inc += t;
    }
    if (lane == 31) wsum[wid] = inc;
    __syncthreads();
    if (wid == 0) {
        int w = (lane < 8) ? wsum[lane] : 0;
#pragma unroll
        for (int d = 1; d < 8; d <<= 1) {
            int t = __shfl_up_sync(0xffffffff, w, d);
            if (lane >= d) w += t;
        }
        if (lane < 8) wsum[lane] = w;
    }
    __syncthreads();
    int excl = inc - tot + (wid ? wsum[wid - 1] : 0);
    if (base + 0 < nseg) g_off[base + 0] = excl;
    if (base + 1 < nseg) g_off[base + 1] = excl + v0;
    if (base + 2 < nseg) g_off[base + 2] = excl + v0 + v1;
    if (base + 3 < nseg) g_off[base + 3] = excl + v0 + v1 + v2;
    if (tid == 255) g_bsum[blockIdx.x] = wsum[7];
}
__global__ void k_scan2t(int nb) {
    __shared__ int sm[1024];
    int tid = threadIdx.x;
    int v = (tid < nb) ? g_bsum[tid] : 0;
    sm[tid] = v;
    __syncthreads();
    for (int d = 1; d < 1024; d <<= 1) {
        int t = (tid >= d) ? sm[tid - d] : 0;
        __syncthreads();
        sm[tid] += t;
        __syncthreads();
    }
    if (tid < nb) g_bsum[tid] = sm[tid] - v;
    if (tid == 0) {
        int a = g_tcnt[0], b = g_tcnt[1], c = g_tcnt[2];
        g_tcur[0] = 0; g_tcur[1] = a; g_tcur[2] = a + b; g_tcur[3] = a + b + c;
        g_tcnt[0] = 0; g_tcnt[1] = 0; g_tcnt[2] = 0; g_tcnt[3] = 0;
        g_ticket = 0;                       // reset work-stealing ticket
    }
}
__global__ void k_scan3z(int nseg) {
    int i = blockIdx.x * blockDim.x + threadIdx.x;
    if (i < nseg) {
        int v = g_off[i] + g_bsum[i >> 10];
        g_cur[i] = v;
        g_offcnt[i] = make_int2(v, g_cnt[i]);
        g_cnt[i] = 0;
    }
}
__global__ void k_scatter2(const int* __restrict__ ei, const int* __restrict__ et,
                           const int* __restrict__ tnt, int E, int Nn, int eb) {
    if ((int)blockIdx.x < eb) {
        int e = blockIdx.x * 256 + threadIdx.x;
        if (e < E) {
            int s = ei[E + e] * RNUM + et[e];
            int p = atomicAdd(&g_cur[s], 1);
            g_esrc[p] = ei[e];
        }
        return;
    }
    __shared__ int loc[4], base[4];
    if (threadIdx.x < 4) loc[threadIdx.x] = 0;
    __syncthreads();
    int i = ((int)blockIdx.x - eb) * 256 + threadIdx.x;
    int t = 0, my = 0;
    bool ok = (i < Nn);
    if (ok) { t = tnt[i]; my = atomicAdd(&loc[t], 1); }
    __syncthreads();
    if (threadIdx.x < 4) base[threadIdx.x] = atomicAdd(&g_tcur[threadIdx.x], loc[threadIdx.x]);
    __syncthreads();
    if (ok) g_perm[base[t] + my] = i;
}

// ---------------- fused: persistent CTAs pulling tiles via atomic ticket ----
__global__ __launch_bounds__(256, 2) void k_fused(const int* __restrict__ tnt,
                                                  const float* __restrict__ root_b,
                                                  float* __restrict__ out,
                                                  int Nn, int ntiles) {
    extern __shared__ char smem[];
    const uint32_t sb = smem_u32(smem);
    int* s_act = reinterpret_cast<int*>(smem + SM_ACT); // [0]=mask [1]=nact [2..15]=list [16]=tile
    const int tid = threadIdx.x, wid = tid >> 5, lane = tid & 31;
    const int wm0 = (wid & 3) * 32;
    const int jbase = (wid >> 2) * 4;
    const int wn0 = jbase * 16;
    const int quad = lane >> 3, lrow = lane & 7;
    const int a_roff = ((quad & 1) * 8 + lrow) * SROW + ((quad >> 1) * 8) * 2;
    const uint2* xh2 = reinterpret_cast<const uint2*>(g_xh);

    for (;;) {
        // ---- grab a tile ----
        if (tid == 0) {
            s_act[16] = atomicAdd(&g_ticket, 1);
            s_act[0] = 0;
        }
        CP_WAIT0();                 // drain previous tile's B pipeline
        __syncthreads();
        const int tile = s_act[16];
        if (tile >= ntiles) return;
        const int row0 = tile * 128;

        float acc[16][4];
#pragma unroll
        for (int j = 0; j < 16; j++)
#pragma unroll
            for (int q = 0; q < 4; q++) acc[j][q] = 0.f;

        // ---- metadata preload (via perm) ----
        int off_s0 = 0, cnt_s0 = 0, off_s1 = 0, cnt_s1 = 0;
        int off_s2 = 0, cnt_s2 = 0, off_s3 = 0, cnt_s3 = 0;
        int mytype = -1, pdstReg = 0;
        {
            const int prow = lane & 15;
            const int grow = row0 + wid * 16 + prow;
            const int ppar = lane >> 4;
            if (grow < Nn) {
                const int pd = g_perm[grow];
                { int2 a = g_offcnt[pd * RNUM + (0 + ppar)]; off_s0 = a.x; cnt_s0 = a.y; }
                { int2 a = g_offcnt[pd * RNUM + (2 + ppar)]; off_s1 = a.x; cnt_s1 = a.y; }
                { int2 a = g_offcnt[pd * RNUM + (4 + ppar)]; off_s2 = a.x; cnt_s2 = a.y; }
                if (ppar == 0) { int2 a = g_offcnt[pd * RNUM + 6]; off_s3 = a.x; cnt_s3 = a.y; }
                if (lane < 16) {
                    pdstReg = pd;
                    mytype = tnt[pd];
                    atomicOr(&s_act[0], 1 << mytype);
                }
            }
        }
        __syncthreads();
        if (tid == 0) {
            const int m = s_act[0];
            int n = 0;
#pragma unroll
            for (int p = 0; p < RNUM; p++) s_act[2 + n++] = p;
#pragma unroll
            for (int t = 0; t < TNUM; t++)
                if (m & (1 << t)) s_act[2 + n++] = RNUM + t;
            s_act[1] = n;
        }
        __syncthreads();
        const int nact = s_act[1];

        // prefetch B phase 0
        {
            const uint4* src = g_Bf;
            const uint32_t d0 = sb + SM_B;
#pragma unroll
            for (int i = 0; i < 8; i++)
                cp16(d0 + (tid + i * 256) * 16, src + tid + i * 256);
            CP_COMMIT();
        }

        // esrc prefetch for phase 0
        int esrcA, esrcB;
        {
            const int r = lane >> 2, j = lane & 3;
            int offa = __shfl_sync(0xffffffffu, off_s0, r);
            int cnta = __shfl_sync(0xffffffffu, cnt_s0, r);
            esrcA = (j < cnta) ? __ldg(&g_esrc[offa + j]) : 0;
            int offb = __shfl_sync(0xffffffffu, off_s0, 8 + r);
            int cntb = __shfl_sync(0xffffffffu, cnt_s0, 8 + r);
            esrcB = (j < cntb) ? __ldg(&g_esrc[offb + j]) : 0;
        }

        for (int ip = 0; ip < nact; ++ip) {
            const int phase = s_act[2 + ip];
            __syncthreads();
            if (ip + 1 < nact) {
                const uint4* src = g_Bf + (size_t)s_act[2 + ip + 1] * 2048;
                const uint32_t d0 = sb + SM_B + ((ip + 1) & 1) * BSTAGE;
#pragma unroll
                for (int i = 0; i < 8; i++)
                    cp16(d0 + (tid + i * 256) * 16, src + tid + i * 256);
            }
            CP_COMMIT();

            if (phase < RNUM) {
                const int slot = phase >> 1;
                const int par = (phase & 1) * 16;
                const int offp = sel4(slot, off_s0, off_s1, off_s2, off_s3);
                const int cntp = sel4(slot, cnt_s0, cnt_s1, cnt_s2, cnt_s3);
#pragma unroll
                for (int i = 0; i < 16; i++) {
                    const int cnt = __shfl_sync(0xffffffffu, cntp, par + i);
                    const int off = __shfl_sync(0xffffffffu, offp, par + i);
                    const int src01 = (i < 8) ? esrcA : esrcB;
                    const int ib = (i & 7) * 4;
                    const int s0 = __shfl_sync(0xffffffffu, src01, ib + 0);
                    const int s1 = __shfl_sync(0xffffffffu, src01, ib + 1);
                    const int s2 = __shfl_sync(0xffffffffu, src01, ib + 2);
                    const int s3 = __shfl_sync(0xffffffffu, src01, ib + 3);
                    __half2 a01 = __float2half2_rn(0.f), a23 = a01;
                    if (cnt > 0) hacc(a01, a23, xh2[(size_t)s0 * 32 + lane]);
                    if (cnt > 1) hacc(a01, a23, xh2[(size_t)s1 * 32 + lane]);
                    if (cnt > 2) hacc(a01, a23, xh2[(size_t)s2 * 32 + lane]);
                    if (cnt > 3) hacc(a01, a23, xh2[(size_t)s3 * 32 + lane]);
                    for (int j = 4; j < cnt; j++)
                        hacc(a01, a23, xh2[(size_t)__ldg(&g_esrc[off + j]) * 32 + lane]);
                    if (cnt > 1) {
                        __half2 hv = __float2half2_rn(1.f / (float)cnt);
                        a01 = __hmul2(a01, hv);
                        a23 = __hmul2(a23, hv);
                    }
                    storeA16(sb, wid * 16 + i, lane, a01, a23);
                }
            } else {
                const int t = phase - RNUM;
#pragma unroll
                for (int i = 0; i < 16; i++) {
                    const int ty = __shfl_sync(0xffffffffu, mytype, i);
                    const int pdst = __shfl_sync(0xffffffffu, pdstReg, i);
                    __half2 a01 = __float2half2_rn(0.f), a23 = a01;
                    if (ty == t) hacc(a01, a23, xh2[(size_t)pdst * 32 + lane]);
                    storeA16(sb, wid * 16 + i, lane, a01, a23);
                }
            }
            if (phase + 1 < RNUM) {
                const int np = phase + 1;
                const int slot = np >> 1;
                const int par = (np & 1) * 16;
                const int offp = sel4(slot, off_s0, off_s1, off_s2, off_s3);
                const int cntp = sel4(slot, cnt_s0, cnt_s1, cnt_s2, cnt_s3);
                const int r = lane >> 2, j = lane & 3;
                int offa = __shfl_sync(0xffffffffu, offp, par + r);
                int cnta = __shfl_sync(0xffffffffu, cntp, par + r);
                esrcA = (j < cnta) ? __ldg(&g_esrc[offa + j]) : 0;
                int offb = __shfl_sync(0xffffffffu, offp, par + 8 + r);
                int cntb = __shfl_sync(0xffffffffu, cntp, par + 8 + r);
                esrcB = (j < cntb) ? __ldg(&g_esrc[offb + j]) : 0;
            }

            CP_WAIT1();
            __syncthreads();
            const uint32_t sbB = sb + SM_B + (ip & 1) * BSTAGE;
#pragma unroll
            for (int cc = 0; cc < 2; cc++) {
#pragma unroll
                for (int s = 0; s < 4; s++) {
                    uint32_t ah0[4], ah1[4];
                    const uint32_t ab0 = sb + cc * ATB + (uint32_t)wm0 * SROW + s * 32 + a_roff;
                    ldmat_x4(ab0, ah0);
                    ldmat_x4(ab0 + 16 * SROW, ah1);
#pragma unroll
                    for (int jp = 0; jp < 4; jp++) {
                        const uint32_t boff = sbB +
                            ((uint32_t)cc * 1024 + ((jbase + jp) * 4 + s) * 32 + lane) * 16;
                        uint4 BH = lds128(boff);
                        mma4(acc[2 * jp],         ah0, BH.x, BH.y);
                        mma4(acc[2 * jp + 1],     ah0, BH.z, BH.w);
                        mma4(acc[8 + 2 * jp],     ah1, BH.x, BH.y);
                        mma4(acc[8 + 2 * jp + 1], ah1, BH.z, BH.w);
                    }
                }
            }
        }

        // ---- epilogue ----
        const int g = lane >> 2, tig = lane & 3;
#pragma unroll
        for (int ms = 0; ms < 2; ms++) {
            const int gr1 = row0 + wm0 + ms * 16 + g;
            const int gr2 = gr1 + 8;
            const int n1 = (gr1 < Nn) ? g_perm[gr1] : 0;
            const int n2 = (gr2 < Nn) ? g_perm[gr2] : 0;
            const int t1 = (gr1 < Nn) ? tnt[n1] : 0;
            const int t2 = (gr2 < Nn) ? tnt[n2] : 0;
#pragma unroll
            for (int nt = 0; nt < 8; nt++) {
                const int col = wn0 + nt * 8 + tig * 2;
                if (gr1 < Nn) {
                    float2 b1 = *reinterpret_cast<const float2*>(root_b + t1 * CDIM + col);
                    *reinterpret_cast<float2*>(out + (size_t)n1 * CDIM + col) =
                        make_float2(acc[ms * 8 + nt][0] + b1.x, acc[ms * 8 + nt][1] + b1.y);
                }
                if (gr2 < Nn) {
                    float2 b2 = *reinterpret_cast<const float2*>(root_b + t2 * CDIM + col);
                    *reinterpret_cast<float2*>(out + (size_t)n2 * CDIM + col) =
                        make_float2(acc[ms * 8 + nt][2] + b2.x, acc[ms * 8 + nt][3] + b2.y);
                }
            }
        }
    }
}

// ---------------------------------------------------------------------------
extern "C" void kernel_launch(void* const* d_in, const int* in_sizes, int n_in,
                              void* d_out, int out_size) {
    const float* x      = (const float*)d_in[0];
    const int*   ei     = (const int*)d_in[1];
    const int*   et     = (const int*)d_in[2];
    const int*   tnt    = (const int*)d_in[3];
    const float* rel_w  = (const float*)d_in[4];
    const float* root_w = (const float*)d_in[5];
    const float* root_b = (const float*)d_in[6];
    float* out = (float*)d_out;

    int E  = in_sizes[2];
    int Nn = in_sizes[3];
    int nseg = Nn * RNUM;
    int nb = (nseg + 1023) / 1024;
    int eb = (E + 255) / 256;
    int tb = (Nn + 255) / 256;
    int bfb = (NCHK * 8 * 4 * 32 + 255) / 256;
    int xw = Nn * 16;
    int cgmax = E > Nn ? E : Nn;
    if (xw > cgmax) cgmax = xw;
    int cg = (cgmax + 255) / 256;
    int ntiles = (Nn + 127) / 128;
    int pgrid = ntiles < 304 ? ntiles : 304;   // 2 CTAs/SM on 148-152 SMs

    cudaFuncSetAttribute(k_fused, cudaFuncAttributeMaxDynamicSharedMemorySize, SM_TOT);

    k_count_t<<<cg, 256>>>(ei, et, tnt, x, E, Nn);
    k_scan1b<<<nb + bfb, 256>>>(nseg, nb, rel_w, root_w);
    k_scan2t<<<1, 1024>>>(nb);
    k_scan3z<<<(nseg + 255) / 256, 256>>>(nseg);
    k_scatter2<<<eb + tb, 256>>>(ei, et, tnt, E, Nn, eb);
    k_fused<<<pgrid, 256, SM_TOT>>>(tnt, root_b, out, Nn, ntiles);
}

// round 17
// speedup vs baseline: 1.4045x; 1.3033x over previous
#include <cuda_runtime.h>
#include <cuda_fp16.h>
#include <cstdint>

#define CDIM 128
#define RNUM 7
#define TNUM 4
#define MAXN 100000
#define MAXE 2000000
#define NPH  (RNUM + TNUM)
#define NCHK 22
#define SROW 144
#define ATB  (128 * SROW)
#define SM_B (2 * ATB)
#define BSTAGE 32768
#define SM_ACT (SM_B + 2 * BSTAGE)
#define SM_SRC (SM_ACT + 96)
#define SM_TOT (SM_SRC + 2048)

// ---------------- device scratch (zero at graph entry — invariant maintained
// by re-zeroing counters after their last read inside each graph execution) --
__device__ int  g_cnt[MAXN * RNUM];
__device__ int  g_off[MAXN * RNUM];
__device__ int  g_cur[MAXN * RNUM];
__device__ int2 g_offcnt[MAXN * RNUM];   // (off, cnt | half(1/max(cnt,1))<<16)
__device__ int  g_bsum[1024];
__device__ int  g_esrc[MAXE];
__device__ int  g_tcnt[4], g_tcur[4];
__device__ int  g_perm[MAXN];
__device__ int  g_ticket;                                    // reset by k_scan2t
__device__ __align__(16) uint32_t g_xh[(size_t)(MAXN + 1) * 64]; // fp16 x + zero sentinel row
__device__ __align__(16) uint4 g_Bf[NCHK * 8 * 4 * 32];

// ---------------- helpers ----------------
__device__ __forceinline__ uint32_t smem_u32(const void* p) {
    uint32_t a;
    asm("{ .reg .u64 t; cvta.to.shared.u64 t, %1; cvt.u32.u64 %0, t; }" : "=r"(a) : "l"(p));
    return a;
}
__device__ __forceinline__ void ldmat_x4(uint32_t addr, uint32_t* r) {
    asm volatile("ldmatrix.sync.aligned.m8n8.x4.shared.b16 {%0,%1,%2,%3}, [%4];"
                 : "=r"(r[0]), "=r"(r[1]), "=r"(r[2]), "=r"(r[3]) : "r"(addr));
}
__device__ __forceinline__ void mma4(float* d, const uint32_t* a, uint32_t b0, uint32_t b1) {
    asm volatile("mma.sync.aligned.m16n8k16.row.col.f32.f16.f16.f32 "
                 "{%0,%1,%2,%3}, {%4,%5,%6,%7}, {%8,%9}, {%0,%1,%2,%3};"
                 : "+f"(d[0]), "+f"(d[1]), "+f"(d[2]), "+f"(d[3])
                 : "r"(a[0]), "r"(a[1]), "r"(a[2]), "r"(a[3]), "r"(b0), "r"(b1));
}
__device__ __forceinline__ uint32_t packh(float a, float b) {
    __half2 h = __floats2half2_rn(a, b);
    return *reinterpret_cast<uint32_t*>(&h);
}
__device__ __forceinline__ uint4 lds128(uint32_t addr) {
    uint4 v;
    asm volatile("ld.shared.v4.b32 {%0,%1,%2,%3}, [%4];"
                 : "=r"(v.x), "=r"(v.y), "=r"(v.z), "=r"(v.w) : "r"(addr));
    return v;
}
__device__ __forceinline__ void sts32(uint32_t addr, uint32_t v) {
    asm volatile("st.shared.b32 [%0], %1;" :: "r"(addr), "r"(v) : "memory");
}
__device__ __forceinline__ void cp16(uint32_t s, const void* g) {
    asm volatile("cp.async.cg.shared.global [%0], [%1], 16;" :: "r"(s), "l"(g));
}
#define CP_COMMIT() asm volatile("cp.async.commit_group;" ::: "memory")
#define CP_WAIT1()  asm volatile("cp.async.wait_group 1;" ::: "memory")
#define CP_WAIT0()  asm volatile("cp.async.wait_group 0;" ::: "memory")

__device__ __forceinline__ int sel4(int s, int a0, int a1, int a2, int a3) {
    int lo = (s & 1) ? a1 : a0;
    int hi = (s & 1) ? a3 : a2;
    return (s & 2) ? hi : lo;
}
__device__ __forceinline__ void hacc(__half2& a01, __half2& a23, uint2 u) {
    a01 = __hadd2(a01, *reinterpret_cast<__half2*>(&u.x));
    a23 = __hadd2(a23, *reinterpret_cast<__half2*>(&u.y));
}
__device__ __forceinline__ void storeA16(uint32_t sbase, int m, int lane,
                                         __half2 a01, __half2 a23) {
    int chunk = lane >> 4;
    uint32_t boff = (uint32_t)m * SROW + (lane & 15) * 8;
    uint32_t r0 = *reinterpret_cast<uint32_t*>(&a01);
    uint32_t r1 = *reinterpret_cast<uint32_t*>(&a23);
    asm volatile("st.shared.v2.b32 [%0], {%1,%2};"
                 :: "r"(sbase + chunk * ATB + boff), "r"(r0), "r"(r1) : "memory");
}

// ---------------- prologue (5 launches) ----------------
__global__ void k_count_t(const int* __restrict__ ei, const int* __restrict__ et,
                          const int* __restrict__ tnt, const float* __restrict__ x,
                          int E, int Nn) {
    __shared__ int h[4];
    if (threadIdx.x < 4) h[threadIdx.x] = 0;
    __syncthreads();
    int i = blockIdx.x * blockDim.x + threadIdx.x;
    if (i < E) atomicAdd(&g_cnt[ei[E + i] * RNUM + et[i]], 1);
    if (i < Nn) atomicAdd(&h[tnt[i]], 1);
    int xi = i * 4;
    if (xi < Nn * 64) {
        const float4* x4 = reinterpret_cast<const float4*>(x);
        float4 fa = x4[xi >> 1];
        float4 fb = x4[(xi >> 1) + 1];
        uint4 o;
        o.x = packh(fa.x, fa.y); o.y = packh(fa.z, fa.w);
        o.z = packh(fb.x, fb.y); o.w = packh(fb.z, fb.w);
        *reinterpret_cast<uint4*>(&g_xh[xi]) = o;
    } else if (xi < (Nn + 1) * 64) {
        *reinterpret_cast<uint4*>(&g_xh[xi]) = make_uint4(0, 0, 0, 0);  // sentinel row
    }
    __syncthreads();
    if (threadIdx.x < 4 && h[threadIdx.x]) atomicAdd(&g_tcnt[threadIdx.x], h[threadIdx.x]);
}
__global__ void k_scan1b(int nseg, int nb,
                         const float* __restrict__ rel_w,
                         const float* __restrict__ root_w) {
    if ((int)blockIdx.x >= nb) {
        int idx = ((int)blockIdx.x - nb) * 256 + threadIdx.x;
        if (idx >= NCHK * 8 * 4 * 32) return;
        int lane = idx & 31;
        int s = (idx >> 5) & 3;
        int j = (idx >> 7) & 7;
        int chunk = idx >> 10;
        uint32_t hq[4];
#pragma unroll
        for (int q = 0; q < 4; q++) {
            int n = j * 16 + ((q & 2) ? 8 : 0) + (lane >> 2);
            int kk = s * 16 + ((q & 1) ? 8 : 0) + 2 * (lane & 3);
            float w0, w1;
            if (chunk < 14) {
                int r = chunk >> 1, kb = (chunk & 1) * 64;
                const float* p = rel_w + ((size_t)(r * CDIM + n)) * CDIM + kb + kk;
                w0 = p[0]; w1 = p[1];
            } else {
                int rc = chunk - 14;
                int t = rc >> 1, kb = (rc & 1) * 64;
                const float* p = root_w + ((size_t)(t * CDIM + n)) * CDIM + kb + kk;
                w0 = p[0]; w1 = p[1];
            }
            hq[q] = packh(w0, w1);
        }
        g_Bf[(((size_t)chunk * 8 + j) * 4 + s) * 32 + lane] =
            make_uint4(hq[0], hq[1], hq[2], hq[3]);
        return;
    }
    __shared__ int wsum[8];
    int tid = threadIdx.x;
    int base = blockIdx.x * 1024 + tid * 4;
    int v0 = 0, v1 = 0, v2 = 0, v3 = 0;
    if (base + 0 < nseg) v0 = g_cnt[base + 0];
    if (base + 1 < nseg) v1 = g_cnt[base + 1];
    if (base + 2 < nseg) v2 = g_cnt[base + 2];
    if (base + 3 < nseg) v3 = g_cnt[base + 3];
    int tot = v0 + v1 + v2 + v3;
    int lane = tid & 31, wid = tid >> 5;
    int inc = tot;
#pragma unroll
    for (int d = 1; d < 32; d <<= 1) {
        int t = __shfl_up_sync(0xffffffff, inc, d);
        if (lane >= d) inc += t;
    }
    if (lane == 31) wsum[wid] = inc;
    __syncthreads();
    if (wid == 0) {
        int w = (lane < 8) ? wsum[lane] : 0;
#pragma unroll
        for (int d = 1; d < 8; d <<= 1) {
            int t = __shfl_up_sync(0xffffffff, w, d);
            if (lane >= d) w += t;
        }
        if (lane < 8) wsum[lane] = w;
    }
    __syncthreads();
    int excl = inc - tot + (wid ? wsum[wid - 1] : 0);
    if (base + 0 < nseg) g_off[base + 0] = excl;
    if (base + 1 < nseg) g_off[base + 1] = excl + v0;
    if (base + 2 < nseg) g_off[base + 2] = excl + v0 + v1;
    if (base + 3 < nseg) g_off[base + 3] = excl + v0 + v1 + v2;
    if (tid == 255) g_bsum[blockIdx.x] = wsum[7];
}
__global__ void k_scan2t(int nb) {
    __shared__ int sm[1024];
    int tid = threadIdx.x;
    int v = (tid < nb) ? g_bsum[tid] : 0;
    sm[tid] = v;
    __syncthreads();
    for (int d = 1; d < 1024; d <<= 1) {
        int t = (tid >= d) ? sm[tid - d] : 0;
        __syncthreads();
        sm[tid] += t;
        __syncthreads();
    }
    if (tid < nb) g_bsum[tid] = sm[tid] - v;
    if (tid == 0) {
        int a = g_tcnt[0], b = g_tcnt[1], c = g_tcnt[2];
        g_tcur[0] = 0; g_tcur[1] = a; g_tcur[2] = a + b; g_tcur[3] = a + b + c;
        g_tcnt[0] = 0; g_tcnt[1] = 0; g_tcnt[2] = 0; g_tcnt[3] = 0;
        g_ticket = 0;
    }
}
__global__ void k_scan3z(int nseg) {
    int i = blockIdx.x * blockDim.x + threadIdx.x;
    if (i < nseg) {
        int v = g_off[i] + g_bsum[i >> 10];
        int c = g_cnt[i];
        g_cur[i] = v;
        __half hv = __float2half(1.f / fmaxf((float)c, 1.f));
        int packed = (c & 0xffff) | ((int)__half_as_ushort(hv) << 16);
        g_offcnt[i] = make_int2(v, packed);
        g_cnt[i] = 0;
    }
}
__global__ void k_scatter2(const int* __restrict__ ei, const int* __restrict__ et,
                           const int* __restrict__ tnt, int E, int Nn, int eb) {
    if ((int)blockIdx.x < eb) {
        int e = blockIdx.x * 256 + threadIdx.x;
        if (e < E) {
            int s = ei[E + e] * RNUM + et[e];
            int p = atomicAdd(&g_cur[s], 1);
            g_esrc[p] = ei[e];
        }
        return;
    }
    __shared__ int loc[4], base[4];
    if (threadIdx.x < 4) loc[threadIdx.x] = 0;
    __syncthreads();
    int i = ((int)blockIdx.x - eb) * 256 + threadIdx.x;
    int t = 0, my = 0;
    bool ok = (i < Nn);
    if (ok) { t = tnt[i]; my = atomicAdd(&loc[t], 1); }
    __syncthreads();
    if (threadIdx.x < 4) base[threadIdx.x] = atomicAdd(&g_tcur[threadIdx.x], loc[threadIdx.x]);
    __syncthreads();
    if (ok) g_perm[base[t] + my] = i;
}

// ---------------- fused: persistent, SMEM-staged srcs, sentinel pads --------
__global__ __launch_bounds__(256, 2) void k_fused(const int* __restrict__ tnt,
                                                  const float* __restrict__ root_b,
                                                  float* __restrict__ out,
                                                  int Nn, int ntiles) {
    extern __shared__ char smem[];
    const uint32_t sb = smem_u32(smem);
    int* s_act = reinterpret_cast<int*>(smem + SM_ACT); // [0]=mask [1]=nact [2..15]=list [16]=tile
    const int tid = threadIdx.x, wid = tid >> 5, lane = tid & 31;
    const int wm0 = (wid & 3) * 32;
    const int jbase = (wid >> 2) * 4;
    const int wn0 = jbase * 16;
    const int quad = lane >> 3, lrow = lane & 7;
    const int a_roff = ((quad & 1) * 8 + lrow) * SROW + ((quad >> 1) * 8) * 2;
    const uint2* xh2 = reinterpret_cast<const uint2*>(g_xh);
    const uint32_t srcBase = sb + SM_SRC + wid * 256;    // 16 rows x int4

    for (;;) {
        if (tid == 0) {
            s_act[16] = atomicAdd(&g_ticket, 1);
            s_act[0] = 0;
        }
        CP_WAIT0();
        __syncthreads();
        const int tile = s_act[16];
        if (tile >= ntiles) return;
        const int row0 = tile * 128;

        float acc[16][4];
#pragma unroll
        for (int j = 0; j < 16; j++)
#pragma unroll
            for (int q = 0; q < 4; q++) acc[j][q] = 0.f;

        // ---- metadata preload (via perm); cv = cnt | half(inv)<<16 ----
        int off_s0 = 0, cv_s0 = 0, off_s1 = 0, cv_s1 = 0;
        int off_s2 = 0, cv_s2 = 0, off_s3 = 0, cv_s3 = 0;
        int mytype = -1, pdstReg = 0;
        {
            const int prow = lane & 15;
            const int grow = row0 + wid * 16 + prow;
            const int ppar = lane >> 4;
            if (grow < Nn) {
                const int pd = g_perm[grow];
                { int2 a = g_offcnt[pd * RNUM + (0 + ppar)]; off_s0 = a.x; cv_s0 = a.y; }
                { int2 a = g_offcnt[pd * RNUM + (2 + ppar)]; off_s1 = a.x; cv_s1 = a.y; }
                { int2 a = g_offcnt[pd * RNUM + (4 + ppar)]; off_s2 = a.x; cv_s2 = a.y; }
                if (ppar == 0) { int2 a = g_offcnt[pd * RNUM + 6]; off_s3 = a.x; cv_s3 = a.y; }
                if (lane < 16) {
                    pdstReg = pd;
                    mytype = tnt[pd];
                    atomicOr(&s_act[0], 1 << mytype);
                }
            }
        }
        __syncthreads();
        if (tid == 0) {
            const int m = s_act[0];
            int n = 0;
#pragma unroll
            for (int p = 0; p < RNUM; p++) s_act[2 + n++] = p;
#pragma unroll
            for (int t = 0; t < TNUM; t++)
                if (m & (1 << t)) s_act[2 + n++] = RNUM + t;
            s_act[1] = n;
        }
        __syncthreads();
        const int nact = s_act[1];

        // prefetch B phase 0
        {
            const uint4* src = g_Bf;
            const uint32_t d0 = sb + SM_B;
#pragma unroll
            for (int i = 0; i < 8; i++)
                cp16(d0 + (tid + i * 256) * 16, src + tid + i * 256);
            CP_COMMIT();
        }

        // esrc prefetch for phase 0 (4 edges/row, sentinel-padded with Nn)
        int esrcA, esrcB;
        {
            const int r = lane >> 2, j = lane & 3;
            int offa = __shfl_sync(0xffffffffu, off_s0, r);
            int cnta = __shfl_sync(0xffffffffu, cv_s0, r) & 0xffff;
            esrcA = (j < cnta) ? __ldg(&g_esrc[offa + j]) : Nn;
            int offb = __shfl_sync(0xffffffffu, off_s0, 8 + r);
            int cntb = __shfl_sync(0xffffffffu, cv_s0, 8 + r) & 0xffff;
            esrcB = (j < cntb) ? __ldg(&g_esrc[offb + j]) : Nn;
        }

        for (int ip = 0; ip < nact; ++ip) {
            const int phase = s_act[2 + ip];
            __syncthreads();
            if (ip + 1 < nact) {
                const uint4* src = g_Bf + (size_t)s_act[2 + ip + 1] * 2048;
                const uint32_t d0 = sb + SM_B + ((ip + 1) & 1) * BSTAGE;
#pragma unroll
                for (int i = 0; i < 8; i++)
                    cp16(d0 + (tid + i * 256) * 16, src + tid + i * 256);
            }
            CP_COMMIT();

            if (phase < RNUM) {
                // dump prefetched srcs to warp-private smem (program-order safe)
                {
                    const int r = lane >> 2, j = lane & 3;
                    sts32(srcBase + (r * 4 + j) * 4, (uint32_t)esrcA);
                    sts32(srcBase + ((8 + r) * 4 + j) * 4, (uint32_t)esrcB);
                }
                // prefetch next relation's srcs (flies under A-build + mma)
                if (phase + 1 < RNUM) {
                    const int np = phase + 1;
                    const int slot = np >> 1;
                    const int par = (np & 1) * 16;
                    const int offp = sel4(slot, off_s0, off_s1, off_s2, off_s3);
                    const int cvp  = sel4(slot, cv_s0, cv_s1, cv_s2, cv_s3);
                    const int r = lane >> 2, j = lane & 3;
                    int offa = __shfl_sync(0xffffffffu, offp, par + r);
                    int cnta = __shfl_sync(0xffffffffu, cvp, par + r) & 0xffff;
                    esrcA = (j < cnta) ? __ldg(&g_esrc[offa + j]) : Nn;
                    int offb = __shfl_sync(0xffffffffu, offp, par + 8 + r);
                    int cntb = __shfl_sync(0xffffffffu, cvp, par + 8 + r) & 0xffff;
                    esrcB = (j < cntb) ? __ldg(&g_esrc[offb + j]) : Nn;
                }
                // build 16 rows from smem srcs: unconditional 4 loads (sentinel=0)
                const int slot = phase >> 1;
                const int par = (phase & 1) * 16;
                const int offp = sel4(slot, off_s0, off_s1, off_s2, off_s3);
                const int cvp  = sel4(slot, cv_s0, cv_s1, cv_s2, cv_s3);
#pragma unroll
                for (int i = 0; i < 16; i++) {
                    const uint4 sv = lds128(srcBase + i * 16);
                    const int cv = __shfl_sync(0xffffffffu, cvp, par + i);
                    const int cnt = cv & 0xffff;
                    __half2 a01 = __float2half2_rn(0.f), a23 = a01;
                    hacc(a01, a23, xh2[(size_t)sv.x * 32 + lane]);
                    hacc(a01, a23, xh2[(size_t)sv.y * 32 + lane]);
                    hacc(a01, a23, xh2[(size_t)sv.z * 32 + lane]);
                    hacc(a01, a23, xh2[(size_t)sv.w * 32 + lane]);
                    if (cnt > 4) {                    // warp-uniform, rare
                        const int off = __shfl_sync(0xffffffffu, offp, par + i);
                        for (int j = 4; j < cnt; j++)
                            hacc(a01, a23, xh2[(size_t)__ldg(&g_esrc[off + j]) * 32 + lane]);
                    }
                    const __half2 hv =
                        __half2half2(__ushort_as_half((unsigned short)(cv >> 16)));
                    a01 = __hmul2(a01, hv);
                    a23 = __hmul2(a23, hv);
                    storeA16(sb, wid * 16 + i, lane, a01, a23);
                }
            } else {
                const int t = phase - RNUM;
#pragma unroll
                for (int i = 0; i < 16; i++) {
                    const int ty = __shfl_sync(0xffffffffu, mytype, i);
                    const int pdst = __shfl_sync(0xffffffffu, pdstReg, i);
                    __half2 a01 = __float2half2_rn(0.f), a23 = a01;
                    if (ty == t) hacc(a01, a23, xh2[(size_t)pdst * 32 + lane]);
                    storeA16(sb, wid * 16 + i, lane, a01, a23);
                }
            }

            CP_WAIT1();
            __syncthreads();
            const uint32_t sbB = sb + SM_B + (ip & 1) * BSTAGE;
#pragma unroll
            for (int cc = 0; cc < 2; cc++) {
#pragma unroll
                for (int s = 0; s < 4; s++) {
                    uint32_t ah0[4], ah1[4];
                    const uint32_t ab0 = sb + cc * ATB + (uint32_t)wm0 * SROW + s * 32 + a_roff;
                    ldmat_x4(ab0, ah0);
                    ldmat_x4(ab0 + 16 * SROW, ah1);
#pragma unroll
                    for (int jp = 0; jp < 4; jp++) {
                        const uint32_t boff = sbB +
                            ((uint32_t)cc * 1024 + ((jbase + jp) * 4 + s) * 32 + lane) * 16;
                        uint4 BH = lds128(boff);
                        mma4(acc[2 * jp],         ah0, BH.x, BH.y);
                        mma4(acc[2 * jp + 1],     ah0, BH.z, BH.w);
                        mma4(acc[8 + 2 * jp],     ah1, BH.x, BH.y);
                        mma4(acc[8 + 2 * jp + 1], ah1, BH.z, BH.w);
                    }
                }
            }
        }

        // ---- epilogue ----
        const int g = lane >> 2, tig = lane & 3;
#pragma unroll
        for (int ms = 0; ms < 2; ms++) {
            const int gr1 = row0 + wm0 + ms * 16 + g;
            const int gr2 = gr1 + 8;
            const int n1 = (gr1 < Nn) ? g_perm[gr1] : 0;
            const int n2 = (gr2 < Nn) ? g_perm[gr2] : 0;
            const int t1 = (gr1 < Nn) ? tnt[n1] : 0;
            const int t2 = (gr2 < Nn) ? tnt[n2] : 0;
#pragma unroll
            for (int nt = 0; nt < 8; nt++) {
                const int col = wn0 + nt * 8 + tig * 2;
                if (gr1 < Nn) {
                    float2 b1 = *reinterpret_cast<const float2*>(root_b + t1 * CDIM + col);
                    *reinterpret_cast<float2*>(out + (size_t)n1 * CDIM + col) =
                        make_float2(acc[ms * 8 + nt][0] + b1.x, acc[ms * 8 + nt][1] + b1.y);
                }
                if (gr2 < Nn) {
                    float2 b2 = *reinterpret_cast<const float2*>(root_b + t2 * CDIM + col);
                    *reinterpret_cast<float2*>(out + (size_t)n2 * CDIM + col) =
                        make_float2(acc[ms * 8 + nt][2] + b2.x, acc[ms * 8 + nt][3] + b2.y);
                }
            }
        }
    }
}

// ---------------------------------------------------------------------------
extern "C" void kernel_launch(void* const* d_in, const int* in_sizes, int n_in,
                              void* d_out, int out_size) {
    const float* x      = (const float*)d_in[0];
    const int*   ei     = (const int*)d_in[1];
    const int*   et     = (const int*)d_in[2];
    const int*   tnt    = (const int*)d_in[3];
    const float* rel_w  = (const float*)d_in[4];
    const float* root_w = (const float*)d_in[5];
    const float* root_b = (const float*)d_in[6];
    float* out = (float*)d_out;

    int E  = in_sizes[2];
    int Nn = in_sizes[3];
    int nseg = Nn * RNUM;
    int nb = (nseg + 1023) / 1024;
    int eb = (E + 255) / 256;
    int tb = (Nn + 255) / 256;
    int bfb = (NCHK * 8 * 4 * 32 + 255) / 256;
    int xw = (Nn + 1) * 16;
    int cgmax = E > Nn ? E : Nn;
    if (xw > cgmax) cgmax = xw;
    int cg = (cgmax + 255) / 256;
    int ntiles = (Nn + 127) / 128;
    int pgrid = ntiles < 304 ? ntiles : 304;

    cudaFuncSetAttribute(k_fused, cudaFuncAttributeMaxDynamicSharedMemorySize, SM_TOT);

    k_count_t<<<cg, 256>>>(ei, et, tnt, x, E, Nn);
    k_scan1b<<<nb + bfb, 256>>>(nseg, nb, rel_w, root_w);
    k_scan2t<<<1, 1024>>>(nb);
    k_scan3z<<<(nseg + 255) / 256, 256>>>(nseg);
    k_scatter2<<<eb + tb, 256>>>(ei, et, tnt, E, Nn, eb);
    k_fused<<<pgrid, 256, SM_TOT>>>(tnt, root_b, out, Nn, ntiles);
}